// round 7
// baseline (speedup 1.0000x reference)
#include <cuda_runtime.h>
#include <cuda_fp16.h>
#include <math.h>
#include <stdint.h>

#define NS 25
#define NQ 50
#define NV 75
#define SEQ 12
#define DIM 1152
#define HH 2
#define DH 576
#define NTUP 220
#define WAY 5
#define SHOT 5
#define KROWS (NQ*NTUP)      /* 11000 */
#define MPAD  11008
#define SKCOL (SHOT*NTUP)    /* 1100 */
#define SKP   1152           /* scores N pad (f16 row) */
#define SKR   1152           /* skz rows pad */
#define KSC   640            /* scores K pad (fp8, 5*128) */
#define KPAD  1152           /* proto K pad (fp8, 9*128) */
#define SMSC  (1.f/24.f)
#define INV256 (1.f/256.f)

// ---------------- device scratch ----------------
__device__ float g_pe[SEQ*DIM];
__device__ int   g_tuples[NTUP*3];
__device__ __align__(16) __half g_Ap[1024*DIM];
__device__ __align__(16) __half g_wT[6912*DIM];
__device__ float g_P[1024*6912];
__device__ __align__(16) uint8_t g_qk8[HH][(size_t)MPAD*KSC];
__device__ __align__(16) uint8_t g_skz8[WAY*HH][(size_t)SKR*KSC];
__device__ __align__(16) uint8_t g_svT8[WAY*HH][(size_t)DH*KPAD];
__device__ float g_qv[(size_t)KROWS*DIM];
__device__ __align__(16) __half g_scores[WAY*HH][(size_t)MPAD*SKP];
__device__ __align__(16) uint8_t g_attn8[WAY*HH][(size_t)MPAD*KPAD];

// ---------------- helpers ----------------
__device__ __forceinline__ uint32_t smem_u32(const void* p){
    uint32_t a;
    asm("{ .reg .u64 t; cvta.to.shared.u64 t, %1; cvt.u32.u64 %0, t; }" : "=r"(a) : "l"(p));
    return a;
}
#define SW128(x) ((x) ^ (((x)>>3)&0x70))

__device__ __forceinline__ void ldm4(uint32_t* r, uint32_t addr){
    asm volatile("ldmatrix.sync.aligned.m8n8.x4.shared.b16 {%0,%1,%2,%3}, [%4];"
        : "=r"(r[0]), "=r"(r[1]), "=r"(r[2]), "=r"(r[3]) : "r"(addr));
}
__device__ __forceinline__ void mma16816h(uint32_t* c, const uint32_t* a, uint32_t b0, uint32_t b1){
    asm volatile("mma.sync.aligned.m16n8k16.row.col.f16.f16.f16.f16 "
        "{%0,%1}, {%2,%3,%4,%5}, {%6,%7}, {%0,%1};"
        : "+r"(c[0]), "+r"(c[1])
        : "r"(a[0]), "r"(a[1]), "r"(a[2]), "r"(a[3]), "r"(b0), "r"(b1));
}
__device__ __forceinline__ void mma16832f8(float* c, const uint32_t* a, uint32_t b0, uint32_t b1){
    asm volatile("mma.sync.aligned.m16n8k32.row.col.f32.e4m3.e4m3.f32 "
        "{%0,%1,%2,%3}, {%4,%5,%6,%7}, {%8,%9}, {%0,%1,%2,%3};"
        : "+f"(c[0]), "+f"(c[1]), "+f"(c[2]), "+f"(c[3])
        : "r"(a[0]), "r"(a[1]), "r"(a[2]), "r"(a[3]), "r"(b0), "r"(b1));
}
__device__ __forceinline__ void cpa16(uint32_t dst, const void* src){
    asm volatile("cp.async.cg.shared.global [%0], [%1], 16;" :: "r"(dst), "l"(src));
}
__device__ __forceinline__ uint8_t f2e4m3(float x){
    uint16_t r;
    asm("cvt.rn.satfinite.e4m3x2.f32 %0, %1, %2;" : "=h"(r) : "f"(0.f), "f"(x));
    return (uint8_t)r;
}
__device__ __forceinline__ uint16_t f2e4m3x2(float lo, float hi){
    uint16_t r;
    asm("cvt.rn.satfinite.e4m3x2.f32 %0, %1, %2;" : "=h"(r) : "f"(hi), "f"(lo));
    return r;
}

// ---------------- init ----------------
__global__ void k_init(float* out) {
    int tid = threadIdx.x;
    for (int i = tid; i < SEQ*576; i += blockDim.x) {
        int p = i / 576, j = i % 576;
        double dv = exp(-(double)(2*j) * (log(10000.0) / 1152.0));
        double ang = (double)p * dv;
        g_pe[p*DIM + 2*j]     = (float)(sin(ang) * 0.1);
        g_pe[p*DIM + 2*j + 1] = (float)(cos(ang) * 0.1);
    }
    if (tid < NQ*WAY) out[tid] = 0.f;
    if (tid == 0) {
        int idx = 0;
        for (int a = 0; a < SEQ; a++)
            for (int b = a+1; b < SEQ; b++)
                for (int c = b+1; c < SEQ; c++) {
                    g_tuples[idx*3+0]=a; g_tuples[idx*3+1]=b; g_tuples[idx*3+2]=c; idx++;
                }
    }
}

__global__ void k_zero16(uint4* p, size_t n){
    size_t i = (size_t)blockIdx.x*256 + threadIdx.x;
    if (i < n) p[i] = make_uint4(0,0,0,0);
}

__global__ __launch_bounds__(128) void k_prepA(const float* __restrict__ sup,
                                               const float* __restrict__ qry){
    int m = blockIdx.x; int v = m/SEQ, f = m%SEQ;
    const float* src = (v < NS) ? sup + (size_t)m*DIM
                                : qry + ((size_t)(v-NS)*SEQ + f)*DIM;
    for (int i = threadIdx.x; i < DIM; i += 128)
        g_Ap[(size_t)m*DIM + i] = __float2half(src[i] + g_pe[f*DIM + i]);
}

__global__ void k_transW(const float* __restrict__ kw, const float* __restrict__ vw){
    __shared__ float t[32][33];
    int z = blockIdx.z; int j = z>>1, which = z&1;
    const float* W = which ? vw : kw;
    int o0 = blockIdx.x*32, k0 = blockIdx.y*32;
    int tx = threadIdx.x, ty = threadIdx.y;
    t[ty][tx] = W[(size_t)(j*1152 + k0 + ty)*1152 + o0 + tx];
    __syncthreads();
    g_wT[(size_t)(j*2304 + which*1152 + o0 + ty)*1152 + k0 + tx] = __float2half(t[tx][ty]);
}

// ---------------- f16 NT GEMM (proj only), f16 acc ----------------
template<int WM, int WN, int GM, int GN, int STAGES>
__global__ __launch_bounds__(256, 2) void k_gemmh(
    const __half* __restrict__ A, int lda,
    const __half* __restrict__ B, int ldb,
    float* __restrict__ C, int ldc, int KT)
{
    constexpr int BN  = GN*WN;
    constexpr int ASZ = 128*128;
    constexpr int BSZ = BN*128;
    constexpr int STG = ASZ + BSZ;
    extern __shared__ char smem[];
    const int tid = threadIdx.x, wid = tid>>5, lane = tid&31;
    const int wm = wid % GM, wn = wid / GM;
    const int m0 = blockIdx.y*128, n0 = blockIdx.x*BN;
    const uint32_t sbase = smem_u32(smem);
    const int lrow = tid >> 3, lch = tid & 7;

    uint32_t acc[WM/16][WN/8][2];
    #pragma unroll
    for (int i=0;i<WM/16;i++) for (int j=0;j<WN/8;j++){ acc[i][j][0]=0u; acc[i][j][1]=0u; }

    auto load_tile = [&](int kt, int buf){
        const __half* Ab = A + (size_t)m0*lda + kt*64;
        const __half* Bb = B + (size_t)n0*ldb + kt*64;
        uint32_t da = sbase + buf*STG;
        uint32_t db = da + ASZ;
        #pragma unroll
        for (int c = 0; c < 4; c++){
            int row = lrow + c*32;
            cpa16(da + SW128(row*128 + lch*16), Ab + (size_t)row*lda + lch*8);
        }
        #pragma unroll
        for (int c = 0; c < BN/32; c++){
            int row = lrow + c*32;
            cpa16(db + SW128(row*128 + lch*16), Bb + (size_t)row*ldb + lch*8);
        }
        asm volatile("cp.async.commit_group;");
    };

    #pragma unroll
    for (int s = 0; s < STAGES-1; s++) load_tile(s, s);

    for (int kt = 0; kt < KT; kt++){
        if (kt + STAGES-1 < KT) load_tile(kt + STAGES-1, (kt + STAGES-1) % STAGES);
        if (kt + 1 >= KT)      asm volatile("cp.async.wait_group 0;");
        else if (STAGES == 2 || kt + 2 >= KT) asm volatile("cp.async.wait_group 1;");
        else                   asm volatile("cp.async.wait_group 2;");
        __syncthreads();
        const uint32_t sA_ = sbase + (kt % STAGES)*STG;
        const uint32_t sB_ = sA_ + ASZ;
        #pragma unroll
        for (int kk = 0; kk < 4; kk++){
            const int colb = kk*32 + ((lane >> 4) << 4);
            uint32_t a[WM/16][4], b[WN/16][4];
            #pragma unroll
            for (int i = 0; i < WM/16; i++)
                ldm4(a[i], sA_ + SW128((wm*WM + i*16 + (lane & 15))*128 + colb));
            #pragma unroll
            for (int j = 0; j < WN/16; j++)
                ldm4(b[j], sB_ + SW128((wn*WN + j*16 + (lane & 15))*128 + colb));
            #pragma unroll
            for (int i = 0; i < WM/16; i++)
                #pragma unroll
                for (int jj = 0; jj < WN/8; jj++)
                    mma16816h(acc[i][jj], a[i], b[jj>>1][jj&1], b[jj>>1][2+(jj&1)]);
        }
        __syncthreads();
    }

    #pragma unroll
    for (int i = 0; i < WM/16; i++){
        int r0 = m0 + wm*WM + i*16 + (lane >> 2);
        #pragma unroll
        for (int jj = 0; jj < WN/8; jj++){
            int cc = n0 + wn*WN + jj*8 + (lane & 3)*2;
            *(float2*)(C + (size_t)r0*ldc + cc)     = __half22float2(*(__half2*)&acc[i][jj][0]);
            *(float2*)(C + (size_t)(r0+8)*ldc + cc) = __half22float2(*(__half2*)&acc[i][jj][1]);
        }
    }
}

// ---------------- fp8 e4m3 NT GEMM, f32 acc, k-tile = 128 elements ----------------
// OT=1: f16 store. OT=2: fused logits with acc*(1/256).
template<int OT, int WM, int WN, int GM, int GN, int STAGES>
__global__ __launch_bounds__(256, 2) void k_gemm8(
    const uint8_t* __restrict__ A, int lda, int amod, size_t sA,
    const uint8_t* __restrict__ B, int ldb, size_t sB,
    void* __restrict__ Cv, int ldc, size_t sC, int KT,
    const float* __restrict__ qv, float* __restrict__ out)
{
    constexpr int BM  = GM*WM;
    constexpr int BN  = GN*WN;
    constexpr int ASZ = BM*128;
    constexpr int BSZ = BN*128;
    constexpr int STG = ASZ + BSZ;
    extern __shared__ char smem[];
    const int tid = threadIdx.x, wid = tid>>5, lane = tid&31;
    const int wm = wid % GM, wn = wid / GM;
    const int z = blockIdx.z;
    A += (size_t)(amod ? (z % amod) : z) * sA;
    B += (size_t)z * sB;
    const int m0 = blockIdx.y*BM, n0 = blockIdx.x*BN;
    const uint32_t sbase = smem_u32(smem);
    const int lrow = tid >> 3, lch = tid & 7;

    float acc[WM/16][WN/8][4];
    #pragma unroll
    for (int i=0;i<WM/16;i++) for (int j=0;j<WN/8;j++)
        #pragma unroll
        for (int r=0;r<4;r++) acc[i][j][r]=0.f;

    auto load_tile = [&](int kt, int buf){
        const uint8_t* Ab = A + (size_t)m0*lda + kt*128;
        const uint8_t* Bb = B + (size_t)n0*ldb + kt*128;
        uint32_t da = sbase + buf*STG;
        uint32_t db = da + ASZ;
        #pragma unroll
        for (int c = 0; c < BM/32; c++){
            int row = lrow + c*32;
            cpa16(da + SW128(row*128 + lch*16), Ab + (size_t)row*lda + lch*16);
        }
        #pragma unroll
        for (int c = 0; c < BN/32; c++){
            int row = lrow + c*32;
            cpa16(db + SW128(row*128 + lch*16), Bb + (size_t)row*ldb + lch*16);
        }
        asm volatile("cp.async.commit_group;");
    };

    #pragma unroll
    for (int s = 0; s < STAGES-1; s++) load_tile(s, s);

    for (int kt = 0; kt < KT; kt++){
        if (kt + STAGES-1 < KT) load_tile(kt + STAGES-1, (kt + STAGES-1) % STAGES);
        if (kt + 1 >= KT)      asm volatile("cp.async.wait_group 0;");
        else if (STAGES == 2 || kt + 2 >= KT) asm volatile("cp.async.wait_group 1;");
        else                   asm volatile("cp.async.wait_group 2;");
        __syncthreads();
        const uint32_t sA_ = sbase + (kt % STAGES)*STG;
        const uint32_t sB_ = sA_ + ASZ;
        #pragma unroll
        for (int kk = 0; kk < 4; kk++){
            const int colb = kk*32 + ((lane >> 4) << 4);   // 32B k-chunk per kk
            uint32_t a[WM/16][4], b[WN/16][4];
            #pragma unroll
            for (int i = 0; i < WM/16; i++)
                ldm4(a[i], sA_ + SW128((wm*WM + i*16 + (lane & 15))*128 + colb));
            #pragma unroll
            for (int j = 0; j < WN/16; j++)
                ldm4(b[j], sB_ + SW128((wn*WN + j*16 + (lane & 15))*128 + colb));
            #pragma unroll
            for (int i = 0; i < WM/16; i++)
                #pragma unroll
                for (int jj = 0; jj < WN/8; jj++)
                    mma16832f8(acc[i][jj], a[i], b[jj>>1][jj&1], b[jj>>1][2+(jj&1)]);
        }
        __syncthreads();
    }

    if (OT == 1) {
        __half* C = (__half*)Cv + (size_t)z * sC;
        #pragma unroll
        for (int i = 0; i < WM/16; i++){
            int r0 = m0 + wm*WM + i*16 + (lane >> 2);
            #pragma unroll
            for (int jj = 0; jj < WN/8; jj++){
                int cc = n0 + wn*WN + jj*8 + (lane & 3)*2;
                *(__half2*)(C + (size_t)r0*ldc + cc)
                    = __floats2half2_rn(acc[i][jj][0], acc[i][jj][1]);
                *(__half2*)(C + (size_t)(r0+8)*ldc + cc)
                    = __floats2half2_rn(acc[i][jj][2], acc[i][jj][3]);
            }
        }
    } else {
        const int w = z >> 1, h = z & 1;
        const int q0 = m0 / NTUP;
        const int qb = (q0 + 1) * NTUP;
        float s0 = 0.f, s1 = 0.f;
        #pragma unroll
        for (int i = 0; i < WM/16; i++){
            int rb = m0 + wm*WM + i*16 + (lane >> 2);
            #pragma unroll
            for (int rr = 0; rr < 2; rr++){
                int row = rb + rr*8;
                if (row < KROWS) {
                    const float* qrow = qv + (size_t)row*DIM + h*DH;
                    float part = 0.f;
                    #pragma unroll
                    for (int jj = 0; jj < WN/8; jj++){
                        int cc = n0 + wn*WN + jj*8 + (lane & 3)*2;
                        float d0 = qrow[cc]   - acc[i][jj][rr*2+0]*INV256;
                        float d1 = qrow[cc+1] - acc[i][jj][rr*2+1]*INV256;
                        part += d0*d0 + d1*d1;
                    }
                    if (row >= qb) s1 += part; else s0 += part;
                }
            }
        }
        float* red = (float*)smem;
        red[tid] = s0; red[256 + tid] = s1;
        __syncthreads();
        #pragma unroll
        for (int st = 128; st > 0; st >>= 1){
            if (tid < st) { red[tid] += red[tid+st]; red[256+tid] += red[256+tid+st]; }
            __syncthreads();
        }
        if (tid == 0 && red[0]   != 0.f) atomicAdd(&out[q0*WAY + w], -red[0]   * (1.f/NTUP));
        if (tid == 1 && q0 + 1 < NQ && red[256] != 0.f)
            atomicAdd(&out[(q0+1)*WAY + w], -red[256] * (1.f/NTUP));
    }
}

// ---------------- tuple combine + bias + LayerNorm, fp8 outputs ----------------
__global__ __launch_bounds__(128) void k_combine(
    const float* __restrict__ kb, const float* __restrict__ vb,
    const float* __restrict__ lg, const float* __restrict__ lb)
{
    const int bid = blockIdx.x;
    const int v = bid / NTUP, t = bid % NTUP;
    const int tid = threadIdx.x;
    __shared__ float red[128];
    __shared__ int fr[3];
    if (tid < 3) fr[tid] = g_tuples[t*3 + tid];
    __syncthreads();

    float kv[9], vv[9];
    float lsum = 0.f, lsq = 0.f;
    #pragma unroll
    for (int ii = 0; ii < 9; ii++) {
        int d = tid + ii*128;
        float ka = kb[d], va = vb[d];
        #pragma unroll
        for (int j = 0; j < 3; j++) {
            const float* p = g_P + (size_t)(v*SEQ + fr[j])*6912 + j*2304;
            ka += p[d]; va += p[1152 + d];
        }
        kv[ii] = ka; vv[ii] = va;
        lsum += ka; lsq += ka*ka;
    }
    red[tid] = lsum; __syncthreads();
    for (int s = 64; s > 0; s >>= 1) { if (tid < s) red[tid] += red[tid+s]; __syncthreads(); }
    float mu = red[0] * (1.f/1152.f);
    __syncthreads();
    red[tid] = lsq; __syncthreads();
    for (int s = 64; s > 0; s >>= 1) { if (tid < s) red[tid] += red[tid+s]; __syncthreads(); }
    float var = red[0] * (1.f/1152.f) - mu*mu;
    float rstd = rsqrtf(var + 1e-5f);

    int w = 0, s = 0;
    if (v < NS) { w = v / SHOT; s = v % SHOT; }
    #pragma unroll
    for (int ii = 0; ii < 9; ii++) {
        int d = tid + ii*128;
        int h = d / DH, dd = d % DH;
        float o = (kv[ii] - mu) * rstd * lg[d] + lb[d];    // raw LN (scale at softmax)
        if (v < NS) {
            int zz = w*2 + h;
            g_skz8[zz][(size_t)(s*NTUP + t)*KSC + dd] = f2e4m3(o);
            g_svT8[zz][(size_t)dd*KPAD + s*NTUP + t] = f2e4m3(vv[ii]);
        } else {
            g_qk8[h][(size_t)((v-NS)*NTUP + t)*KSC + dd] = f2e4m3(o);
            g_qv[(size_t)((v-NS)*NTUP + t)*DIM + d] = vv[ii];
        }
    }
}

// ---------------- softmax: f16 scores -> e4m3 attn (x256), warp per row ----------------
__global__ __launch_bounds__(256) void k_softmax() {
    const int row = blockIdx.x*8 + (threadIdx.x >> 5);
    const int lane = threadIdx.x & 31;
    const int z = row / KROWS, r = row % KROWS;
    const __half2* src = (const __half2*)(g_scores[z] + (size_t)r * SKP);
    uint16_t* dst = (uint16_t*)(g_attn8[z] + (size_t)r * KPAD);
    float e0[18], e1[18];
    float mx = -1e30f;
    #pragma unroll
    for (int ii = 0; ii < 18; ii++){
        int i = lane + ii*32;
        if (i < 550) {
            float2 v = __half22float2(src[i]);
            e0[ii] = v.x * SMSC; e1[ii] = v.y * SMSC;
            mx = fmaxf(mx, fmaxf(e0[ii], e1[ii]));
        } else { e0[ii] = -1e30f; e1[ii] = -1e30f; }
    }
    #pragma unroll
    for (int o = 16; o; o >>= 1) mx = fmaxf(mx, __shfl_xor_sync(0xffffffffu, mx, o));
    float sum = 0.f;
    #pragma unroll
    for (int ii = 0; ii < 18; ii++){
        int i = lane + ii*32;
        if (i < 550) {
            e0[ii] = __expf(e0[ii] - mx);
            e1[ii] = __expf(e1[ii] - mx);
            sum += e0[ii] + e1[ii];
        } else { e0[ii] = 0.f; e1[ii] = 0.f; }
    }
    #pragma unroll
    for (int o = 16; o; o >>= 1) sum += __shfl_xor_sync(0xffffffffu, sum, o);
    float inv = 256.f / sum;   // x256 fp8 scale folded here
    #pragma unroll
    for (int ii = 0; ii < 18; ii++){
        int i = lane + ii*32;
        if (i < 576) dst[i] = f2e4m3x2(e0[ii]*inv, e1[ii]*inv);
    }
}

// ---------------- launch ----------------
extern "C" void kernel_launch(void* const* d_in, const int* in_sizes, int n_in,
                              void* d_out, int out_size)
{
    const float* support = (const float*)d_in[0];
    const float* queries = (const float*)d_in[1];
    const float* k_w  = (const float*)d_in[3];
    const float* k_b  = (const float*)d_in[4];
    const float* v_w  = (const float*)d_in[5];
    const float* v_b  = (const float*)d_in[6];
    const float* ln_g = (const float*)d_in[7];
    const float* ln_b = (const float*)d_in[8];
    float* out = (float*)d_out;

    void *pAp, *pWT, *pP, *pQK, *pSKZ, *pSVT, *pSC, *pATT, *pQV;
    cudaGetSymbolAddress(&pAp,  g_Ap);
    cudaGetSymbolAddress(&pWT,  g_wT);
    cudaGetSymbolAddress(&pP,   g_P);
    cudaGetSymbolAddress(&pQK,  g_qk8);
    cudaGetSymbolAddress(&pSKZ, g_skz8);
    cudaGetSymbolAddress(&pSVT, g_svT8);
    cudaGetSymbolAddress(&pSC,  g_scores);
    cudaGetSymbolAddress(&pATT, g_attn8);
    cudaGetSymbolAddress(&pQV,  g_qv);

    auto gemm_pp = k_gemmh<32,64,4,2,3>;        // proj f16
    auto gemm_sc = k_gemm8<1,32,64,4,2,3>;      // scores fp8, CTA 128x128
    auto gemm_pr = k_gemm8<2,32,48,4,2,3>;      // proto fp8,  CTA 128x96
    cudaFuncSetAttribute(gemm_pp, cudaFuncAttributeMaxDynamicSharedMemorySize, 3*32768);
    cudaFuncSetAttribute(gemm_sc, cudaFuncAttributeMaxDynamicSharedMemorySize, 3*32768);
    cudaFuncSetAttribute(gemm_pr, cudaFuncAttributeMaxDynamicSharedMemorySize, 3*28672);

    k_init<<<1, 256>>>(out);
    {   // zero fp8 operand arrays (K/N pads must be 0)
        size_t n1 = (size_t)HH*MPAD*KSC/16;
        k_zero16<<<(int)((n1 + 255)/256), 256>>>((uint4*)pQK, n1);
        size_t n2 = (size_t)WAY*HH*SKR*KSC/16;
        k_zero16<<<(int)((n2 + 255)/256), 256>>>((uint4*)pSKZ, n2);
        size_t n3 = (size_t)WAY*HH*DH*KPAD/16;
        k_zero16<<<(int)((n3 + 255)/256), 256>>>((uint4*)pSVT, n3);
    }
    k_prepA<<<NV*SEQ, 128>>>(support, queries);
    k_transW<<<dim3(36, 36, 6), dim3(32, 32)>>>(k_w, v_w);

    // proj: C[1024(900), 6912] = Ap @ wT^T, K=1152, f16 mma, fp32 out
    gemm_pp<<<dim3(54, 8, 1), 256, 3*32768>>>(
        (const __half*)pAp, DIM, (const __half*)pWT, DIM,
        (float*)pP, 6912, 18);

    k_combine<<<NV*NTUP, 128>>>(k_b, v_b, ln_g, ln_b);

    // scores fp8: per z: C[11008, 1152] = qk8[z%2] @ skz8[z]^T, K=640 (5 k-tiles)
    gemm_sc<<<dim3(SKP/128, MPAD/128, WAY*HH), 256, 3*32768>>>(
        (const uint8_t*)pQK, KSC, 2, (size_t)MPAD*KSC,
        (const uint8_t*)pSKZ, KSC, (size_t)SKR*KSC,
        pSC, SKP, (size_t)MPAD*SKP, 5, nullptr, nullptr);

    k_softmax<<<WAY*HH*KROWS/8, 256>>>();

    // proto fp8 + fused logits: per z: P[11008,576] = attn8[z] @ svT8[z]^T, K=1152 (9 k-tiles)
    gemm_pr<<<dim3(DH/96, MPAD/128, WAY*HH), 256, 3*28672>>>(
        (const uint8_t*)pATT, KPAD, 0, (size_t)MPAD*KPAD,
        (const uint8_t*)pSVT, KPAD, (size_t)DH*KPAD,
        nullptr, 0, 0, 9, (const float*)pQV, out);
}

// round 8
// speedup vs baseline: 1.0573x; 1.0573x over previous
#include <cuda_runtime.h>
#include <cuda_fp16.h>
#include <math.h>
#include <stdint.h>

#define NS 25
#define NQ 50
#define NV 75
#define SEQ 12
#define DIM 1152
#define HH 2
#define DH 576
#define NTUP 220
#define WAY 5
#define SHOT 5
#define KROWS (NQ*NTUP)      /* 11000 */
#define MPAD  11008
#define SKCOL (SHOT*NTUP)    /* 1100 */
#define SKP   1152
#define KPAD  1152
#define RS24  0.20412414523193154f   /* 1/sqrt(24) */

// ---------------- device scratch (zero-initialized; pads stay zero) ----------------
__device__ float g_pe[SEQ*DIM];
__device__ int   g_tuples[NTUP*3];
__device__ __align__(16) __half g_Ap[1024*DIM];
__device__ __align__(16) __half g_wT[6912*DIM];
__device__ float g_P[1024*6912];
__device__ __align__(16) __half g_qk[HH][(size_t)MPAD*DH];
__device__ __align__(16) __half g_skz[WAY*HH][(size_t)SKP*DH];
__device__ __align__(16) __half g_svT[WAY*HH][(size_t)DH*KPAD];
__device__ float g_qv[(size_t)KROWS*DIM];
__device__ __align__(16) __half g_scores[WAY*HH][(size_t)MPAD*SKP];
__device__ __align__(16) __half g_attn[WAY*HH][(size_t)MPAD*KPAD];

// ---------------- helpers ----------------
__device__ __forceinline__ uint32_t smem_u32(const void* p){
    uint32_t a;
    asm("{ .reg .u64 t; cvta.to.shared.u64 t, %1; cvt.u32.u64 %0, t; }" : "=r"(a) : "l"(p));
    return a;
}
#define SW128(x) ((x) ^ (((x)>>3)&0x70))

__device__ __forceinline__ void ldm4(uint32_t* r, uint32_t addr){
    asm volatile("ldmatrix.sync.aligned.m8n8.x4.shared.b16 {%0,%1,%2,%3}, [%4];"
        : "=r"(r[0]), "=r"(r[1]), "=r"(r[2]), "=r"(r[3]) : "r"(addr));
}
__device__ __forceinline__ void mma16816h(uint32_t* c, const uint32_t* a, uint32_t b0, uint32_t b1){
    asm volatile("mma.sync.aligned.m16n8k16.row.col.f16.f16.f16.f16 "
        "{%0,%1}, {%2,%3,%4,%5}, {%6,%7}, {%0,%1};"
        : "+r"(c[0]), "+r"(c[1])
        : "r"(a[0]), "r"(a[1]), "r"(a[2]), "r"(a[3]), "r"(b0), "r"(b1));
}
__device__ __forceinline__ void cpa16(uint32_t dst, const void* src){
    asm volatile("cp.async.cg.shared.global [%0], [%1], 16;" :: "r"(dst), "l"(src));
}

// ---------------- init ----------------
__global__ void k_init(float* out) {
    int tid = threadIdx.x;
    for (int i = tid; i < SEQ*576; i += blockDim.x) {
        int p = i / 576, j = i % 576;
        double dv = exp(-(double)(2*j) * (log(10000.0) / 1152.0));
        double ang = (double)p * dv;
        g_pe[p*DIM + 2*j]     = (float)(sin(ang) * 0.1);
        g_pe[p*DIM + 2*j + 1] = (float)(cos(ang) * 0.1);
    }
    if (tid < NQ*WAY) out[tid] = 0.f;
    if (tid == 0) {
        int idx = 0;
        for (int a = 0; a < SEQ; a++)
            for (int b = a+1; b < SEQ; b++)
                for (int c = b+1; c < SEQ; c++) {
                    g_tuples[idx*3+0]=a; g_tuples[idx*3+1]=b; g_tuples[idx*3+2]=c; idx++;
                }
    }
}

__global__ __launch_bounds__(128) void k_prepA(const float* __restrict__ sup,
                                               const float* __restrict__ qry){
    int m = blockIdx.x; int v = m/SEQ, f = m%SEQ;
    const float* src = (v < NS) ? sup + (size_t)m*DIM
                                : qry + ((size_t)(v-NS)*SEQ + f)*DIM;
    for (int i = threadIdx.x; i < DIM; i += 128)
        g_Ap[(size_t)m*DIM + i] = __float2half(src[i] + g_pe[f*DIM + i]);
}

__global__ void k_transW(const float* __restrict__ kw, const float* __restrict__ vw){
    __shared__ float t[32][33];
    int z = blockIdx.z; int j = z>>1, which = z&1;
    const float* W = which ? vw : kw;
    int o0 = blockIdx.x*32, k0 = blockIdx.y*32;
    int tx = threadIdx.x, ty = threadIdx.y;
    t[ty][tx] = W[(size_t)(j*1152 + k0 + ty)*1152 + o0 + tx];
    __syncthreads();
    g_wT[(size_t)(j*2304 + which*1152 + o0 + ty)*1152 + k0 + tx] = __float2half(t[tx][ty]);
}

// ---------------- f16 NT GEMM, f16 acc, pipelined cp.async ----------------
// C[M,N] = A[M,K] @ B[N,K]^T. CTA tile (GM*WM) x (GN*WN). 8 warps. K = KT*64.
// OT=0: fp32 store. OT=1: f16 store. OT=2: fused -(qv-C)^2 logits.
template<int OT, int WM, int WN, int GM, int GN, int STAGES>
__global__ __launch_bounds__(256, 2) void k_gemmh(
    const __half* __restrict__ A, int lda, int amod, size_t sA,
    const __half* __restrict__ B, int ldb, size_t sB,
    void* __restrict__ Cv, int ldc, size_t sC, int KT, int zbase,
    const float* __restrict__ qv, float* __restrict__ out)
{
    constexpr int BM  = GM*WM;
    constexpr int BN  = GN*WN;
    constexpr int ASZ = BM*128;
    constexpr int BSZ = BN*128;
    constexpr int STG = ASZ + BSZ;
    extern __shared__ char smem[];
    const int tid = threadIdx.x, wid = tid>>5, lane = tid&31;
    const int wm = wid % GM, wn = wid / GM;
    const int z = zbase + blockIdx.z;
    A += (size_t)(amod ? (z % amod) : z) * sA;
    B += (size_t)z * sB;
    const int m0 = blockIdx.y*BM, n0 = blockIdx.x*BN;
    const uint32_t sbase = smem_u32(smem);
    const int lrow = tid >> 3, lch = tid & 7;

    uint32_t acc[WM/16][WN/8][2];
    #pragma unroll
    for (int i=0;i<WM/16;i++) for (int j=0;j<WN/8;j++){ acc[i][j][0]=0u; acc[i][j][1]=0u; }

    auto load_tile = [&](int kt, int buf){
        const __half* Ab = A + (size_t)m0*lda + kt*64;
        const __half* Bb = B + (size_t)n0*ldb + kt*64;
        uint32_t da = sbase + buf*STG;
        uint32_t db = da + ASZ;
        #pragma unroll
        for (int c = 0; c < BM/32; c++){
            int row = lrow + c*32;
            cpa16(da + SW128(row*128 + lch*16), Ab + (size_t)row*lda + lch*8);
        }
        #pragma unroll
        for (int c = 0; c < BN/32; c++){
            int row = lrow + c*32;
            cpa16(db + SW128(row*128 + lch*16), Bb + (size_t)row*ldb + lch*8);
        }
        asm volatile("cp.async.commit_group;");
    };

    #pragma unroll
    for (int s = 0; s < STAGES-1; s++) load_tile(s, s);

    for (int kt = 0; kt < KT; kt++){
        if (kt + STAGES-1 < KT) load_tile(kt + STAGES-1, (kt + STAGES-1) % STAGES);
        if (kt + 1 >= KT)      asm volatile("cp.async.wait_group 0;");
        else if (STAGES == 2 || kt + 2 >= KT) asm volatile("cp.async.wait_group 1;");
        else                   asm volatile("cp.async.wait_group 2;");
        __syncthreads();
        const uint32_t sA_ = sbase + (kt % STAGES)*STG;
        const uint32_t sB_ = sA_ + ASZ;
        #pragma unroll
        for (int kk = 0; kk < 4; kk++){
            const int colb = kk*32 + ((lane >> 4) << 4);
            uint32_t a[WM/16][4], b[WN/16][4];
            #pragma unroll
            for (int i = 0; i < WM/16; i++)
                ldm4(a[i], sA_ + SW128((wm*WM + i*16 + (lane & 15))*128 + colb));
            #pragma unroll
            for (int j = 0; j < WN/16; j++)
                ldm4(b[j], sB_ + SW128((wn*WN + j*16 + (lane & 15))*128 + colb));
            #pragma unroll
            for (int i = 0; i < WM/16; i++)
                #pragma unroll
                for (int jj = 0; jj < WN/8; jj++)
                    mma16816h(acc[i][jj], a[i], b[jj>>1][jj&1], b[jj>>1][2+(jj&1)]);
        }
        __syncthreads();
    }

    if (OT == 0) {
        float* C = (float*)Cv + (size_t)z * sC;
        #pragma unroll
        for (int i = 0; i < WM/16; i++){
            int r0 = m0 + wm*WM + i*16 + (lane >> 2);
            #pragma unroll
            for (int jj = 0; jj < WN/8; jj++){
                int cc = n0 + wn*WN + jj*8 + (lane & 3)*2;
                *(float2*)(C + (size_t)r0*ldc + cc)     = __half22float2(*(__half2*)&acc[i][jj][0]);
                *(float2*)(C + (size_t)(r0+8)*ldc + cc) = __half22float2(*(__half2*)&acc[i][jj][1]);
            }
        }
    } else if (OT == 1) {
        __half* C = (__half*)Cv + (size_t)z * sC;
        #pragma unroll
        for (int i = 0; i < WM/16; i++){
            int r0 = m0 + wm*WM + i*16 + (lane >> 2);
            #pragma unroll
            for (int jj = 0; jj < WN/8; jj++){
                int cc = n0 + wn*WN + jj*8 + (lane & 3)*2;
                *(uint32_t*)(C + (size_t)r0*ldc + cc)     = acc[i][jj][0];
                *(uint32_t*)(C + (size_t)(r0+8)*ldc + cc) = acc[i][jj][1];
            }
        }
    } else {
        const int w = z >> 1, h = z & 1;
        const int q0 = m0 / NTUP;
        const int qb = (q0 + 1) * NTUP;
        float s0 = 0.f, s1 = 0.f;
        #pragma unroll
        for (int i = 0; i < WM/16; i++){
            int rb = m0 + wm*WM + i*16 + (lane >> 2);
            #pragma unroll
            for (int rr = 0; rr < 2; rr++){
                int row = rb + rr*8;
                if (row < KROWS) {
                    const float* qrow = qv + (size_t)row*DIM + h*DH;
                    float part = 0.f;
                    #pragma unroll
                    for (int jj = 0; jj < WN/8; jj++){
                        int cc = n0 + wn*WN + jj*8 + (lane & 3)*2;
                        float2 v = __half22float2(*(__half2*)&acc[i][jj][rr]);
                        float d0 = qrow[cc]   - v.x;
                        float d1 = qrow[cc+1] - v.y;
                        part += d0*d0 + d1*d1;
                    }
                    if (row >= qb) s1 += part; else s0 += part;
                }
            }
        }
        float* red = (float*)smem;
        red[tid] = s0; red[256 + tid] = s1;
        __syncthreads();
        #pragma unroll
        for (int st = 128; st > 0; st >>= 1){
            if (tid < st) { red[tid] += red[tid+st]; red[256+tid] += red[256+tid+st]; }
            __syncthreads();
        }
        if (tid == 0 && red[0]   != 0.f) atomicAdd(&out[q0*WAY + w], -red[0]   * (1.f/NTUP));
        if (tid == 1 && q0 + 1 < NQ && red[256] != 0.f)
            atomicAdd(&out[(q0+1)*WAY + w], -red[256] * (1.f/NTUP));
    }
}

// ---------------- tuple combine + bias + LayerNorm ----------------
__global__ __launch_bounds__(128) void k_combine(
    const float* __restrict__ kb, const float* __restrict__ vb,
    const float* __restrict__ lg, const float* __restrict__ lb)
{
    const int bid = blockIdx.x;
    const int v = bid / NTUP, t = bid % NTUP;
    const int tid = threadIdx.x;
    __shared__ float red[128];
    __shared__ int fr[3];
    if (tid < 3) fr[tid] = g_tuples[t*3 + tid];
    __syncthreads();

    float kv[9], vv[9];
    float lsum = 0.f, lsq = 0.f;
    #pragma unroll
    for (int ii = 0; ii < 9; ii++) {
        int d = tid + ii*128;
        float ka = kb[d], va = vb[d];
        #pragma unroll
        for (int j = 0; j < 3; j++) {
            const float* p = g_P + (size_t)(v*SEQ + fr[j])*6912 + j*2304;
            ka += p[d]; va += p[1152 + d];
        }
        kv[ii] = ka; vv[ii] = va;
        lsum += ka; lsq += ka*ka;
    }
    red[tid] = lsum; __syncthreads();
    for (int s = 64; s > 0; s >>= 1) { if (tid < s) red[tid] += red[tid+s]; __syncthreads(); }
    float mu = red[0] * (1.f/1152.f);
    __syncthreads();
    red[tid] = lsq; __syncthreads();
    for (int s = 64; s > 0; s >>= 1) { if (tid < s) red[tid] += red[tid+s]; __syncthreads(); }
    float var = red[0] * (1.f/1152.f) - mu*mu;
    float rstd = rsqrtf(var + 1e-5f);

    int w = 0, s = 0;
    if (v < NS) { w = v / SHOT; s = v % SHOT; }
    #pragma unroll
    for (int ii = 0; ii < 9; ii++) {
        int d = tid + ii*128;
        int h = d / DH, dd = d % DH;
        float o = ((kv[ii] - mu) * rstd * lg[d] + lb[d]) * RS24;  // fold 1/sqrt(24) both sides
        if (v < NS) {
            int zz = w*2 + h;
            g_skz[zz][(size_t)(s*NTUP + t)*DH + dd] = __float2half(o);
            g_svT[zz][(size_t)dd*KPAD + s*NTUP + t] = __float2half(vv[ii]);
        } else {
            g_qk[h][(size_t)((v-NS)*NTUP + t)*DH + dd] = __float2half(o);
            g_qv[(size_t)((v-NS)*NTUP + t)*DIM + d] = vv[ii];
        }
    }
}

// ---------------- softmax: warp/row, no max pass, f16x2 ex2 ----------------
__global__ __launch_bounds__(256) void k_softmax(int zbase) {
    const int gr = blockIdx.x*8 + (threadIdx.x >> 5);
    const int lane = threadIdx.x & 31;
    const int z = zbase + gr / KROWS, r = gr % KROWS;
    const uint32_t* src = (const uint32_t*)(g_scores[z] + (size_t)r * SKP);
    __half2* dst = (__half2*)(g_attn[z] + (size_t)r * KPAD);
    const __half2 l2e = __float2half2_rn(1.44269504f);
    __half2 e[18];
    float sum = 0.f;
    #pragma unroll
    for (int ii = 0; ii < 18; ii++){
        int i = lane + ii*32;
        if (i < 550) {
            uint32_t in = src[i];
            __half2 hm = __hmul2(*(__half2*)&in, l2e);
            uint32_t o;
            asm("ex2.approx.f16x2 %0, %1;" : "=r"(o) : "r"(*(uint32_t*)&hm));
            e[ii] = *(__half2*)&o;
            float2 f = __half22float2(e[ii]);
            sum += f.x + f.y;
        } else e[ii] = __float2half2_rn(0.f);
    }
    #pragma unroll
    for (int o = 16; o; o >>= 1) sum += __shfl_xor_sync(0xffffffffu, sum, o);
    __half2 inv = __float2half2_rn(1.f / sum);
    #pragma unroll
    for (int ii = 0; ii < 18; ii++){
        int i = lane + ii*32;
        if (i < 576) dst[i] = __hmul2(e[ii], inv);
    }
}

// ---------------- launch ----------------
extern "C" void kernel_launch(void* const* d_in, const int* in_sizes, int n_in,
                              void* d_out, int out_size)
{
    const float* support = (const float*)d_in[0];
    const float* queries = (const float*)d_in[1];
    const float* k_w  = (const float*)d_in[3];
    const float* k_b  = (const float*)d_in[4];
    const float* v_w  = (const float*)d_in[5];
    const float* v_b  = (const float*)d_in[6];
    const float* ln_g = (const float*)d_in[7];
    const float* ln_b = (const float*)d_in[8];
    float* out = (float*)d_out;

    void *pAp, *pWT, *pP, *pQK, *pSKZ, *pSVT, *pSC, *pATT, *pQV;
    cudaGetSymbolAddress(&pAp,  g_Ap);
    cudaGetSymbolAddress(&pWT,  g_wT);
    cudaGetSymbolAddress(&pP,   g_P);
    cudaGetSymbolAddress(&pQK,  g_qk);
    cudaGetSymbolAddress(&pSKZ, g_skz);
    cudaGetSymbolAddress(&pSVT, g_svT);
    cudaGetSymbolAddress(&pSC,  g_scores);
    cudaGetSymbolAddress(&pATT, g_attn);
    cudaGetSymbolAddress(&pQV,  g_qv);

    auto gemm_pp = k_gemmh<0,32,64,4,2,3>;   // proj
    auto gemm_sc = k_gemmh<1,32,64,4,2,3>;   // scores
    auto gemm_pr = k_gemmh<2,64,48,2,4,2>;   // proto+logits
    cudaFuncSetAttribute(gemm_pp, cudaFuncAttributeMaxDynamicSharedMemorySize, 3*32768);
    cudaFuncSetAttribute(gemm_sc, cudaFuncAttributeMaxDynamicSharedMemorySize, 3*32768);
    cudaFuncSetAttribute(gemm_pr, cudaFuncAttributeMaxDynamicSharedMemorySize, 2*40960);

    // side stream + events for softmax/GEMM overlap (created per call; not destroyed
    // so capture-referenced objects stay valid; kernel_launch runs only a few times)
    cudaStream_t s1;
    cudaStreamCreateWithFlags(&s1, cudaStreamNonBlocking);
    cudaEvent_t eSL, eSmL, eSH, eSmH;
    cudaEventCreateWithFlags(&eSL,  cudaEventDisableTiming);
    cudaEventCreateWithFlags(&eSmL, cudaEventDisableTiming);
    cudaEventCreateWithFlags(&eSH,  cudaEventDisableTiming);
    cudaEventCreateWithFlags(&eSmH, cudaEventDisableTiming);

    k_init<<<1, 256>>>(out);
    k_prepA<<<NV*SEQ, 128>>>(support, queries);
    k_transW<<<dim3(36, 36, 6), dim3(32, 32)>>>(k_w, v_w);

    // proj: C[1024(900), 6912] = Ap @ wT^T, K=1152
    gemm_pp<<<dim3(54, 8, 1), 256, 3*32768>>>(
        (const __half*)pAp, DIM, 1, 0,
        (const __half*)pWT, DIM, 0,
        pP, 6912, 0, 18, 0, nullptr, nullptr);

    k_combine<<<NV*NTUP, 128>>>(k_b, v_b, ln_g, ln_b);

    // ---- pipelined attention: z in [0,5) then [5,10) ----
    // scores_lo
    gemm_sc<<<dim3(9, 86, 5), 256, 3*32768>>>(
        (const __half*)pQK, DH, 2, (size_t)MPAD*DH,
        (const __half*)pSKZ, DH, (size_t)SKP*DH,
        pSC, SKP, (size_t)MPAD*SKP, 9, 0, nullptr, nullptr);
    cudaEventRecord(eSL, 0);

    // softmax_lo on side stream (overlaps scores_hi)
    cudaStreamWaitEvent(s1, eSL, 0);
    k_softmax<<<5*KROWS/8, 256, 0, s1>>>(0);
    cudaEventRecord(eSmL, s1);

    // scores_hi
    gemm_sc<<<dim3(9, 86, 5), 256, 3*32768>>>(
        (const __half*)pQK, DH, 2, (size_t)MPAD*DH,
        (const __half*)pSKZ, DH, (size_t)SKP*DH,
        pSC, SKP, (size_t)MPAD*SKP, 9, 5, nullptr, nullptr);
    cudaEventRecord(eSH, 0);

    // softmax_hi on side stream (overlaps proto_lo)
    cudaStreamWaitEvent(s1, eSH, 0);
    k_softmax<<<5*KROWS/8, 256, 0, s1>>>(5);
    cudaEventRecord(eSmH, s1);

    // proto_lo (needs softmax_lo)
    cudaStreamWaitEvent(0, eSmL, 0);
    gemm_pr<<<dim3(3, 86, 5), 256, 2*40960>>>(
        (const __half*)pATT, KPAD, 0, (size_t)MPAD*KPAD,
        (const __half*)pSVT, KPAD, (size_t)DH*KPAD,
        nullptr, 0, 0, 18, 0, (const float*)pQV, out);

    // proto_hi (needs softmax_hi)
    cudaStreamWaitEvent(0, eSmH, 0);
    gemm_pr<<<dim3(3, 86, 5), 256, 2*40960>>>(
        (const __half*)pATT, KPAD, 0, (size_t)MPAD*KPAD,
        (const __half*)pSVT, KPAD, (size_t)DH*KPAD,
        nullptr, 0, 0, 18, 5, (const float*)pQV, out);
}

// round 9
// speedup vs baseline: 1.1382x; 1.0765x over previous
#include <cuda_runtime.h>
#include <cuda_fp16.h>
#include <math.h>
#include <stdint.h>

#define NS 25
#define NQ 50
#define NV 75
#define SEQ 12
#define DIM 1152
#define HH 2
#define DH 576
#define NTUP 220
#define WAY 5
#define SHOT 5
#define KROWS (NQ*NTUP)      /* 11000 */
#define MPAD  11008
#define SKCOL (SHOT*NTUP)    /* 1100 */
#define SKP   1152
#define KPAD  1152
#define RS24  0.20412414523193154f   /* 1/sqrt(24) folded into q and k */

// ---------------- device scratch (zero-initialized; pads stay zero) ----------------
__device__ float g_pe[SEQ*DIM];
__device__ int   g_tuples[NTUP*3];
__device__ __align__(16) __half g_Ap[1024*DIM];
__device__ __align__(16) __half g_wT[6912*DIM];
__device__ float g_P[1024*6912];
__device__ __align__(16) __half g_qk[HH][(size_t)MPAD*DH];
__device__ __align__(16) __half g_skz[WAY*HH][(size_t)SKP*DH];
__device__ __align__(16) __half g_svT[WAY*HH][(size_t)DH*KPAD];
__device__ float g_qv[(size_t)KROWS*DIM];
__device__ __align__(16) __half g_attn[WAY*HH][(size_t)MPAD*KPAD];   // exp(scores), unnormalized
__device__ float g_rowsum[WAY*HH][MPAD];

// ---------------- helpers ----------------
__device__ __forceinline__ uint32_t smem_u32(const void* p){
    uint32_t a;
    asm("{ .reg .u64 t; cvta.to.shared.u64 t, %1; cvt.u32.u64 %0, t; }" : "=r"(a) : "l"(p));
    return a;
}
#define SW128(x) ((x) ^ (((x)>>3)&0x70))

__device__ __forceinline__ void ldm4(uint32_t* r, uint32_t addr){
    asm volatile("ldmatrix.sync.aligned.m8n8.x4.shared.b16 {%0,%1,%2,%3}, [%4];"
        : "=r"(r[0]), "=r"(r[1]), "=r"(r[2]), "=r"(r[3]) : "r"(addr));
}
__device__ __forceinline__ void mma16816h(uint32_t* c, const uint32_t* a, uint32_t b0, uint32_t b1){
    asm volatile("mma.sync.aligned.m16n8k16.row.col.f16.f16.f16.f16 "
        "{%0,%1}, {%2,%3,%4,%5}, {%6,%7}, {%0,%1};"
        : "+r"(c[0]), "+r"(c[1])
        : "r"(a[0]), "r"(a[1]), "r"(a[2]), "r"(a[3]), "r"(b0), "r"(b1));
}
__device__ __forceinline__ void cpa16(uint32_t dst, const void* src){
    asm volatile("cp.async.cg.shared.global [%0], [%1], 16;" :: "r"(dst), "l"(src));
}
__device__ __forceinline__ uint32_t h2ex2(uint32_t h){
    uint32_t o;
    asm("ex2.approx.f16x2 %0, %1;" : "=r"(o) : "r"(h));
    return o;
}

// ---------------- init ----------------
__global__ void k_init(float* out) {
    int tid = threadIdx.x;
    for (int i = tid; i < SEQ*576; i += blockDim.x) {
        int p = i / 576, j = i % 576;
        double dv = exp(-(double)(2*j) * (log(10000.0) / 1152.0));
        double ang = (double)p * dv;
        g_pe[p*DIM + 2*j]     = (float)(sin(ang) * 0.1);
        g_pe[p*DIM + 2*j + 1] = (float)(cos(ang) * 0.1);
    }
    if (tid < NQ*WAY) out[tid] = 0.f;
    if (tid == 0) {
        int idx = 0;
        for (int a = 0; a < SEQ; a++)
            for (int b = a+1; b < SEQ; b++)
                for (int c = b+1; c < SEQ; c++) {
                    g_tuples[idx*3+0]=a; g_tuples[idx*3+1]=b; g_tuples[idx*3+2]=c; idx++;
                }
    }
}

// zero rowsum every launch (graph replays)
__global__ void k_zrs(){
    int i = blockIdx.x*256 + threadIdx.x;
    if (i < WAY*HH*MPAD) ((float*)g_rowsum)[i] = 0.f;
}

__global__ __launch_bounds__(128) void k_prepA(const float* __restrict__ sup,
                                               const float* __restrict__ qry){
    int m = blockIdx.x; int v = m/SEQ, f = m%SEQ;
    const float* src = (v < NS) ? sup + (size_t)m*DIM
                                : qry + ((size_t)(v-NS)*SEQ + f)*DIM;
    for (int i = threadIdx.x; i < DIM; i += 128)
        g_Ap[(size_t)m*DIM + i] = __float2half(src[i] + g_pe[f*DIM + i]);
}

// weight transpose, 256-thread blocks, 4 elems/thread
__global__ __launch_bounds__(256) void k_transW(const float* __restrict__ kw,
                                                const float* __restrict__ vw){
    __shared__ float t[32][33];
    int z = blockIdx.z; int j = z>>1, which = z&1;
    const float* W = which ? vw : kw;
    int o0 = blockIdx.x*32, k0 = blockIdx.y*32;
    int tx = threadIdx.x & 31, ty = threadIdx.x >> 5;   // 32 x 8
    #pragma unroll
    for (int r = 0; r < 4; r++)
        t[ty + r*8][tx] = W[(size_t)(j*1152 + k0 + ty + r*8)*1152 + o0 + tx];
    __syncthreads();
    #pragma unroll
    for (int r = 0; r < 4; r++)
        g_wT[(size_t)(j*2304 + which*1152 + o0 + ty + r*8)*1152 + k0 + tx]
            = __float2half(t[tx][ty + r*8]);
}

// ---------------- f16 NT GEMM, f16 acc, pipelined cp.async ----------------
// C[M,N] = A[M,K] @ B[N,K]^T. CTA tile (GM*WM) x (GN*WN). 8 warps. K = KT*64.
// OT=0: fp32 store. OT=1: exp-f16 store + rowsum atomics. OT=2: normalize + logits.
template<int OT, int WM, int WN, int GM, int GN, int STAGES>
__global__ __launch_bounds__(256, 2) void k_gemmh(
    const __half* __restrict__ A, int lda, int amod, size_t sA,
    const __half* __restrict__ B, int ldb, size_t sB,
    void* __restrict__ Cv, int ldc, size_t sC, int KT,
    const float* __restrict__ qv, float* __restrict__ out, float* __restrict__ rsum)
{
    constexpr int BM  = GM*WM;
    constexpr int BN  = GN*WN;
    constexpr int ASZ = BM*128;
    constexpr int BSZ = BN*128;
    constexpr int STG = ASZ + BSZ;
    extern __shared__ char smem[];
    const int tid = threadIdx.x, wid = tid>>5, lane = tid&31;
    const int wm = wid % GM, wn = wid / GM;
    const int z = blockIdx.z;
    A += (size_t)(amod ? (z % amod) : z) * sA;
    B += (size_t)z * sB;
    const int m0 = blockIdx.y*BM, n0 = blockIdx.x*BN;
    const uint32_t sbase = smem_u32(smem);
    const int lrow = tid >> 3, lch = tid & 7;

    uint32_t acc[WM/16][WN/8][2];
    #pragma unroll
    for (int i=0;i<WM/16;i++) for (int j=0;j<WN/8;j++){ acc[i][j][0]=0u; acc[i][j][1]=0u; }

    auto load_tile = [&](int kt, int buf){
        const __half* Ab = A + (size_t)m0*lda + kt*64;
        const __half* Bb = B + (size_t)n0*ldb + kt*64;
        uint32_t da = sbase + buf*STG;
        uint32_t db = da + ASZ;
        #pragma unroll
        for (int c = 0; c < BM/32; c++){
            int row = lrow + c*32;
            cpa16(da + SW128(row*128 + lch*16), Ab + (size_t)row*lda + lch*8);
        }
        #pragma unroll
        for (int c = 0; c < BN/32; c++){
            int row = lrow + c*32;
            cpa16(db + SW128(row*128 + lch*16), Bb + (size_t)row*ldb + lch*8);
        }
        asm volatile("cp.async.commit_group;");
    };

    #pragma unroll
    for (int s = 0; s < STAGES-1; s++) load_tile(s, s);

    for (int kt = 0; kt < KT; kt++){
        if (kt + STAGES-1 < KT) load_tile(kt + STAGES-1, (kt + STAGES-1) % STAGES);
        if (kt + 1 >= KT)      asm volatile("cp.async.wait_group 0;");
        else if (STAGES == 2 || kt + 2 >= KT) asm volatile("cp.async.wait_group 1;");
        else                   asm volatile("cp.async.wait_group 2;");
        __syncthreads();
        const uint32_t sA_ = sbase + (kt % STAGES)*STG;
        const uint32_t sB_ = sA_ + ASZ;
        #pragma unroll
        for (int kk = 0; kk < 4; kk++){
            const int colb = kk*32 + ((lane >> 4) << 4);
            uint32_t a[WM/16][4], b[WN/16][4];
            #pragma unroll
            for (int i = 0; i < WM/16; i++)
                ldm4(a[i], sA_ + SW128((wm*WM + i*16 + (lane & 15))*128 + colb));
            #pragma unroll
            for (int j = 0; j < WN/16; j++)
                ldm4(b[j], sB_ + SW128((wn*WN + j*16 + (lane & 15))*128 + colb));
            #pragma unroll
            for (int i = 0; i < WM/16; i++)
                #pragma unroll
                for (int jj = 0; jj < WN/8; jj++)
                    mma16816h(acc[i][jj], a[i], b[jj>>1][jj&1], b[jj>>1][2+(jj&1)]);
        }
        __syncthreads();
    }

    if (OT == 0) {
        float* C = (float*)Cv + (size_t)z * sC;
        #pragma unroll
        for (int i = 0; i < WM/16; i++){
            int r0 = m0 + wm*WM + i*16 + (lane >> 2);
            #pragma unroll
            for (int jj = 0; jj < WN/8; jj++){
                int cc = n0 + wn*WN + jj*8 + (lane & 3)*2;
                *(float2*)(C + (size_t)r0*ldc + cc)     = __half22float2(*(__half2*)&acc[i][jj][0]);
                *(float2*)(C + (size_t)(r0+8)*ldc + cc) = __half22float2(*(__half2*)&acc[i][jj][1]);
            }
        }
    } else if (OT == 1) {
        // exp + masked store to attn + per-row partial sums
        __half* C = (__half*)Cv + (size_t)z * sC;
        const uint32_t L2E = 0x3dc53dc5u;  // half2(1.4427)
        float rs[WM/16][2];
        #pragma unroll
        for (int i=0;i<WM/16;i++){ rs[i][0]=0.f; rs[i][1]=0.f; }
        #pragma unroll
        for (int i = 0; i < WM/16; i++){
            int r0 = m0 + wm*WM + i*16 + (lane >> 2);
            #pragma unroll
            for (int jj = 0; jj < WN/8; jj++){
                int cc = n0 + wn*WN + jj*8 + (lane & 3)*2;
                uint32_t e0 = 0u, e1 = 0u;
                if (cc < SKCOL) {
                    __half2 m0h = __hmul2(*(__half2*)&acc[i][jj][0], *(__half2*)&L2E);
                    __half2 m1h = __hmul2(*(__half2*)&acc[i][jj][1], *(__half2*)&L2E);
                    e0 = h2ex2(*(uint32_t*)&m0h);
                    e1 = h2ex2(*(uint32_t*)&m1h);
                    float2 f0 = __half22float2(*(__half2*)&e0);
                    float2 f1 = __half22float2(*(__half2*)&e1);
                    rs[i][0] += f0.x + f0.y;
                    rs[i][1] += f1.x + f1.y;
                }
                *(uint32_t*)(C + (size_t)r0*ldc + cc)     = e0;
                *(uint32_t*)(C + (size_t)(r0+8)*ldc + cc) = e1;
            }
        }
        float* rz = rsum + (size_t)z * MPAD;
        #pragma unroll
        for (int i = 0; i < WM/16; i++){
            int r0 = m0 + wm*WM + i*16 + (lane >> 2);
            #pragma unroll
            for (int rr = 0; rr < 2; rr++){
                float s = rs[i][rr];
                s += __shfl_xor_sync(0xffffffffu, s, 1);
                s += __shfl_xor_sync(0xffffffffu, s, 2);
                if ((lane & 3) == 0 && s != 0.f) atomicAdd(&rz[r0 + rr*8], s);
            }
        }
    } else {
        const int w = z >> 1, h = z & 1;
        const int q0 = m0 / NTUP;
        const int qb = (q0 + 1) * NTUP;
        const float* rz = rsum + (size_t)z * MPAD;
        float s0 = 0.f, s1 = 0.f;
        #pragma unroll
        for (int i = 0; i < WM/16; i++){
            int rb = m0 + wm*WM + i*16 + (lane >> 2);
            #pragma unroll
            for (int rr = 0; rr < 2; rr++){
                int row = rb + rr*8;
                if (row < KROWS) {
                    const float inv = 1.f / rz[row];
                    const float* qrow = qv + (size_t)row*DIM + h*DH;
                    float part = 0.f;
                    #pragma unroll
                    for (int jj = 0; jj < WN/8; jj++){
                        int cc = n0 + wn*WN + jj*8 + (lane & 3)*2;
                        float2 v = __half22float2(*(__half2*)&acc[i][jj][rr]);
                        float d0 = qrow[cc]   - v.x*inv;
                        float d1 = qrow[cc+1] - v.y*inv;
                        part += d0*d0 + d1*d1;
                    }
                    if (row >= qb) s1 += part; else s0 += part;
                }
            }
        }
        float* red = (float*)smem;
        red[tid] = s0; red[256 + tid] = s1;
        __syncthreads();
        #pragma unroll
        for (int st = 128; st > 0; st >>= 1){
            if (tid < st) { red[tid] += red[tid+st]; red[256+tid] += red[256+tid+st]; }
            __syncthreads();
        }
        if (tid == 0 && red[0]   != 0.f) atomicAdd(&out[q0*WAY + w], -red[0]   * (1.f/NTUP));
        if (tid == 1 && q0 + 1 < NQ && red[256] != 0.f)
            atomicAdd(&out[(q0+1)*WAY + w], -red[256] * (1.f/NTUP));
    }
}

// ---------------- tuple combine + bias + LayerNorm ----------------
__global__ __launch_bounds__(128) void k_combine(
    const float* __restrict__ kb, const float* __restrict__ vb,
    const float* __restrict__ lg, const float* __restrict__ lb)
{
    const int bid = blockIdx.x;
    const int v = bid / NTUP, t = bid % NTUP;
    const int tid = threadIdx.x;
    __shared__ float red[128];
    __shared__ int fr[3];
    if (tid < 3) fr[tid] = g_tuples[t*3 + tid];
    __syncthreads();

    float kv[9], vv[9];
    float lsum = 0.f, lsq = 0.f;
    #pragma unroll
    for (int ii = 0; ii < 9; ii++) {
        int d = tid + ii*128;
        float ka = kb[d], va = vb[d];
        #pragma unroll
        for (int j = 0; j < 3; j++) {
            const float* p = g_P + (size_t)(v*SEQ + fr[j])*6912 + j*2304;
            ka += p[d]; va += p[1152 + d];
        }
        kv[ii] = ka; vv[ii] = va;
        lsum += ka; lsq += ka*ka;
    }
    red[tid] = lsum; __syncthreads();
    for (int s = 64; s > 0; s >>= 1) { if (tid < s) red[tid] += red[tid+s]; __syncthreads(); }
    float mu = red[0] * (1.f/1152.f);
    __syncthreads();
    red[tid] = lsq; __syncthreads();
    for (int s = 64; s > 0; s >>= 1) { if (tid < s) red[tid] += red[tid+s]; __syncthreads(); }
    float var = red[0] * (1.f/1152.f) - mu*mu;
    float rstd = rsqrtf(var + 1e-5f);

    int w = 0, s = 0;
    if (v < NS) { w = v / SHOT; s = v % SHOT; }
    #pragma unroll
    for (int ii = 0; ii < 9; ii++) {
        int d = tid + ii*128;
        int h = d / DH, dd = d % DH;
        float o = ((kv[ii] - mu) * rstd * lg[d] + lb[d]) * RS24;
        if (v < NS) {
            int zz = w*2 + h;
            g_skz[zz][(size_t)(s*NTUP + t)*DH + dd] = __float2half(o);
            g_svT[zz][(size_t)dd*KPAD + s*NTUP + t] = __float2half(vv[ii]);
        } else {
            g_qk[h][(size_t)((v-NS)*NTUP + t)*DH + dd] = __float2half(o);
            g_qv[(size_t)((v-NS)*NTUP + t)*DIM + d] = vv[ii];
        }
    }
}

// ---------------- launch ----------------
extern "C" void kernel_launch(void* const* d_in, const int* in_sizes, int n_in,
                              void* d_out, int out_size)
{
    const float* support = (const float*)d_in[0];
    const float* queries = (const float*)d_in[1];
    const float* k_w  = (const float*)d_in[3];
    const float* k_b  = (const float*)d_in[4];
    const float* v_w  = (const float*)d_in[5];
    const float* v_b  = (const float*)d_in[6];
    const float* ln_g = (const float*)d_in[7];
    const float* ln_b = (const float*)d_in[8];
    float* out = (float*)d_out;

    void *pAp, *pWT, *pP, *pQK, *pSKZ, *pSVT, *pATT, *pQV, *pRS;
    cudaGetSymbolAddress(&pAp,  g_Ap);
    cudaGetSymbolAddress(&pWT,  g_wT);
    cudaGetSymbolAddress(&pP,   g_P);
    cudaGetSymbolAddress(&pQK,  g_qk);
    cudaGetSymbolAddress(&pSKZ, g_skz);
    cudaGetSymbolAddress(&pSVT, g_svT);
    cudaGetSymbolAddress(&pATT, g_attn);
    cudaGetSymbolAddress(&pQV,  g_qv);
    cudaGetSymbolAddress(&pRS,  g_rowsum);

    auto gemm_pp = k_gemmh<0,32,64,4,2,3>;   // proj
    auto gemm_sc = k_gemmh<1,32,64,4,2,3>;   // scores -> exp + rowsum
    auto gemm_pr = k_gemmh<2,64,48,2,4,2>;   // proto + normalize + logits
    cudaFuncSetAttribute(gemm_pp, cudaFuncAttributeMaxDynamicSharedMemorySize, 3*32768);
    cudaFuncSetAttribute(gemm_sc, cudaFuncAttributeMaxDynamicSharedMemorySize, 3*32768);
    cudaFuncSetAttribute(gemm_pr, cudaFuncAttributeMaxDynamicSharedMemorySize, 2*40960);

    k_init<<<1, 256>>>(out);
    k_zrs<<<(WAY*HH*MPAD + 255)/256, 256>>>();
    k_prepA<<<NV*SEQ, 128>>>(support, queries);
    k_transW<<<dim3(36, 36, 6), 256>>>(k_w, v_w);

    // proj: C[1024(900), 6912] = Ap @ wT^T, K=1152
    gemm_pp<<<dim3(54, 8, 1), 256, 3*32768>>>(
        (const __half*)pAp, DIM, 1, 0,
        (const __half*)pWT, DIM, 0,
        pP, 6912, 0, 18, nullptr, nullptr, nullptr);

    k_combine<<<NV*NTUP, 128>>>(k_b, v_b, ln_g, ln_b);

    // scores: per z: attn[11008,1152] = exp(qk[z%2] @ skz[z]^T), rowsum accumulated
    gemm_sc<<<dim3(9, 86, WAY*HH), 256, 3*32768>>>(
        (const __half*)pQK, DH, 2, (size_t)MPAD*DH,
        (const __half*)pSKZ, DH, (size_t)SKP*DH,
        pATT, SKP, (size_t)MPAD*SKP, 9, nullptr, nullptr, (float*)pRS);

    // proto + normalize + fused logits
    gemm_pr<<<dim3(3, 86, WAY*HH), 256, 2*40960>>>(
        (const __half*)pATT, KPAD, 0, (size_t)MPAD*KPAD,
        (const __half*)pSVT, KPAD, (size_t)DH*KPAD,
        nullptr, 0, 0, 18, (const float*)pQV, out, (float*)pRS);
}

// round 10
// speedup vs baseline: 1.1662x; 1.0246x over previous
#include <cuda_runtime.h>
#include <cuda_fp16.h>
#include <math.h>
#include <stdint.h>

#define NS 25
#define NQ 50
#define NV 75
#define SEQ 12
#define DIM 1152
#define HH 2
#define DH 576
#define NTUP 220
#define WAY 5
#define SHOT 5
#define KROWS (NQ*NTUP)      /* 11000 */
#define MPAD  11008
#define SKCOL (SHOT*NTUP)    /* 1100 */
#define SKP   1152
#define KPAD  1152
#define RS24  0.20412414523193154f   /* 1/sqrt(24) folded into q and k */

// ---------------- device scratch (zero-initialized; pads stay zero) ----------------
__device__ float g_pe[SEQ*DIM];
__device__ int   g_tuples[NTUP*3];
__device__ __align__(16) __half g_Ap[1024*DIM];
__device__ __align__(16) __half g_wT[6912*DIM];
__device__ __align__(16) __half g_P[(size_t)1024*6912];
__device__ __align__(16) __half g_qk[HH][(size_t)MPAD*DH];
__device__ __align__(16) __half g_skz[WAY*HH][(size_t)SKP*DH];
__device__ __align__(16) __half g_svT[WAY*HH][(size_t)DH*KPAD];
__device__ __align__(16) __half g_qv[(size_t)KROWS*DIM];
__device__ __align__(16) __half g_attn[WAY*HH][(size_t)MPAD*KPAD];   // exp(scores), unnormalized
__device__ float g_rowsum[WAY*HH][MPAD];

// ---------------- helpers ----------------
__device__ __forceinline__ uint32_t smem_u32(const void* p){
    uint32_t a;
    asm("{ .reg .u64 t; cvta.to.shared.u64 t, %1; cvt.u32.u64 %0, t; }" : "=r"(a) : "l"(p));
    return a;
}
#define SW128(x) ((x) ^ (((x)>>3)&0x70))

__device__ __forceinline__ void ldm4(uint32_t* r, uint32_t addr){
    asm volatile("ldmatrix.sync.aligned.m8n8.x4.shared.b16 {%0,%1,%2,%3}, [%4];"
        : "=r"(r[0]), "=r"(r[1]), "=r"(r[2]), "=r"(r[3]) : "r"(addr));
}
__device__ __forceinline__ void mma16816h(uint32_t* c, const uint32_t* a, uint32_t b0, uint32_t b1){
    asm volatile("mma.sync.aligned.m16n8k16.row.col.f16.f16.f16.f16 "
        "{%0,%1}, {%2,%3,%4,%5}, {%6,%7}, {%0,%1};"
        : "+r"(c[0]), "+r"(c[1])
        : "r"(a[0]), "r"(a[1]), "r"(a[2]), "r"(a[3]), "r"(b0), "r"(b1));
}
__device__ __forceinline__ void cpa16(uint32_t dst, const void* src){
    asm volatile("cp.async.cg.shared.global [%0], [%1], 16;" :: "r"(dst), "l"(src));
}
__device__ __forceinline__ uint32_t h2ex2(uint32_t h){
    uint32_t o;
    asm("ex2.approx.f16x2 %0, %1;" : "=r"(o) : "r"(h));
    return o;
}

// ---------------- init ----------------
__global__ void k_init(float* out) {
    int tid = threadIdx.x;
    for (int i = tid; i < SEQ*576; i += blockDim.x) {
        int p = i / 576, j = i % 576;
        double dv = exp(-(double)(2*j) * (log(10000.0) / 1152.0));
        double ang = (double)p * dv;
        g_pe[p*DIM + 2*j]     = (float)(sin(ang) * 0.1);
        g_pe[p*DIM + 2*j + 1] = (float)(cos(ang) * 0.1);
    }
    if (tid < NQ*WAY) out[tid] = 0.f;
    if (tid == 0) {
        int idx = 0;
        for (int a = 0; a < SEQ; a++)
            for (int b = a+1; b < SEQ; b++)
                for (int c = b+1; c < SEQ; c++) {
                    g_tuples[idx*3+0]=a; g_tuples[idx*3+1]=b; g_tuples[idx*3+2]=c; idx++;
                }
    }
}

// zero rowsum every launch (graph replays re-accumulate)
__global__ void k_zrs(){
    int i = blockIdx.x*256 + threadIdx.x;
    if (i < WAY*HH*MPAD) ((float*)g_rowsum)[i] = 0.f;
}

__global__ __launch_bounds__(128) void k_prepA(const float* __restrict__ sup,
                                               const float* __restrict__ qry){
    int m = blockIdx.x; int v = m/SEQ, f = m%SEQ;
    const float* src = (v < NS) ? sup + (size_t)m*DIM
                                : qry + ((size_t)(v-NS)*SEQ + f)*DIM;
    for (int i = threadIdx.x; i < DIM; i += 128)
        g_Ap[(size_t)m*DIM + i] = __float2half(src[i] + g_pe[f*DIM + i]);
}

__global__ __launch_bounds__(256) void k_transW(const float* __restrict__ kw,
                                                const float* __restrict__ vw){
    __shared__ float t[32][33];
    int z = blockIdx.z; int j = z>>1, which = z&1;
    const float* W = which ? vw : kw;
    int o0 = blockIdx.x*32, k0 = blockIdx.y*32;
    int tx = threadIdx.x & 31, ty = threadIdx.x >> 5;   // 32 x 8
    #pragma unroll
    for (int r = 0; r < 4; r++)
        t[ty + r*8][tx] = W[(size_t)(j*1152 + k0 + ty + r*8)*1152 + o0 + tx];
    __syncthreads();
    #pragma unroll
    for (int r = 0; r < 4; r++)
        g_wT[(size_t)(j*2304 + which*1152 + o0 + ty + r*8)*1152 + k0 + tx]
            = __float2half(t[tx][ty + r*8]);
}

// ---------------- f16 NT GEMM, f16 acc, pipelined cp.async ----------------
// C[M,N] = A[M,K] @ B[N,K]^T. CTA tile (GM*WM) x (GN*WN). 8 warps. K = KT*64.
// OT=0: raw f16 store. OT=1: exp-f16 store + rowsum atomics. OT=2: normalize + logits.
template<int OT, int WM, int WN, int GM, int GN, int STAGES>
__global__ __launch_bounds__(256, 2) void k_gemmh(
    const __half* __restrict__ A, int lda, int amod, size_t sA,
    const __half* __restrict__ B, int ldb, size_t sB,
    void* __restrict__ Cv, int ldc, size_t sC, int KT,
    const __half* __restrict__ qv, float* __restrict__ out, float* __restrict__ rsum)
{
    constexpr int BM  = GM*WM;
    constexpr int BN  = GN*WN;
    constexpr int ASZ = BM*128;
    constexpr int BSZ = BN*128;
    constexpr int STG = ASZ + BSZ;
    extern __shared__ char smem[];
    const int tid = threadIdx.x, wid = tid>>5, lane = tid&31;
    const int wm = wid % GM, wn = wid / GM;
    const int z = blockIdx.z;
    A += (size_t)(amod ? (z % amod) : z) * sA;
    B += (size_t)z * sB;
    const int m0 = blockIdx.y*BM, n0 = blockIdx.x*BN;
    const uint32_t sbase = smem_u32(smem);
    const int lrow = tid >> 3, lch = tid & 7;

    uint32_t acc[WM/16][WN/8][2];
    #pragma unroll
    for (int i=0;i<WM/16;i++) for (int j=0;j<WN/8;j++){ acc[i][j][0]=0u; acc[i][j][1]=0u; }

    auto load_tile = [&](int kt, int buf){
        const __half* Ab = A + (size_t)m0*lda + kt*64;
        const __half* Bb = B + (size_t)n0*ldb + kt*64;
        uint32_t da = sbase + buf*STG;
        uint32_t db = da + ASZ;
        #pragma unroll
        for (int c = 0; c < BM/32; c++){
            int row = lrow + c*32;
            cpa16(da + SW128(row*128 + lch*16), Ab + (size_t)row*lda + lch*8);
        }
        #pragma unroll
        for (int c = 0; c < BN/32; c++){
            int row = lrow + c*32;
            cpa16(db + SW128(row*128 + lch*16), Bb + (size_t)row*ldb + lch*8);
        }
        asm volatile("cp.async.commit_group;");
    };

    #pragma unroll
    for (int s = 0; s < STAGES-1; s++) load_tile(s, s);

    for (int kt = 0; kt < KT; kt++){
        if (kt + STAGES-1 < KT) load_tile(kt + STAGES-1, (kt + STAGES-1) % STAGES);
        if (kt + 1 >= KT)      asm volatile("cp.async.wait_group 0;");
        else if (STAGES == 2 || kt + 2 >= KT) asm volatile("cp.async.wait_group 1;");
        else                   asm volatile("cp.async.wait_group 2;");
        __syncthreads();
        const uint32_t sA_ = sbase + (kt % STAGES)*STG;
        const uint32_t sB_ = sA_ + ASZ;
        #pragma unroll
        for (int kk = 0; kk < 4; kk++){
            const int colb = kk*32 + ((lane >> 4) << 4);
            uint32_t a[WM/16][4], b[WN/16][4];
            #pragma unroll
            for (int i = 0; i < WM/16; i++)
                ldm4(a[i], sA_ + SW128((wm*WM + i*16 + (lane & 15))*128 + colb));
            #pragma unroll
            for (int j = 0; j < WN/16; j++)
                ldm4(b[j], sB_ + SW128((wn*WN + j*16 + (lane & 15))*128 + colb));
            #pragma unroll
            for (int i = 0; i < WM/16; i++)
                #pragma unroll
                for (int jj = 0; jj < WN/8; jj++)
                    mma16816h(acc[i][jj], a[i], b[jj>>1][jj&1], b[jj>>1][2+(jj&1)]);
        }
        __syncthreads();
    }

    if (OT == 0) {
        __half* C = (__half*)Cv + (size_t)z * sC;
        #pragma unroll
        for (int i = 0; i < WM/16; i++){
            int r0 = m0 + wm*WM + i*16 + (lane >> 2);
            #pragma unroll
            for (int jj = 0; jj < WN/8; jj++){
                int cc = n0 + wn*WN + jj*8 + (lane & 3)*2;
                *(uint32_t*)(C + (size_t)r0*ldc + cc)     = acc[i][jj][0];
                *(uint32_t*)(C + (size_t)(r0+8)*ldc + cc) = acc[i][jj][1];
            }
        }
    } else if (OT == 1) {
        __half* C = (__half*)Cv + (size_t)z * sC;
        const uint32_t L2E = 0x3dc53dc5u;  // half2(1.4427)
        float rs[WM/16][2];
        #pragma unroll
        for (int i=0;i<WM/16;i++){ rs[i][0]=0.f; rs[i][1]=0.f; }
        #pragma unroll
        for (int i = 0; i < WM/16; i++){
            int r0 = m0 + wm*WM + i*16 + (lane >> 2);
            #pragma unroll
            for (int jj = 0; jj < WN/8; jj++){
                int cc = n0 + wn*WN + jj*8 + (lane & 3)*2;
                uint32_t e0 = 0u, e1 = 0u;
                if (cc < SKCOL) {
                    __half2 m0h = __hmul2(*(__half2*)&acc[i][jj][0], *(__half2*)&L2E);
                    __half2 m1h = __hmul2(*(__half2*)&acc[i][jj][1], *(__half2*)&L2E);
                    e0 = h2ex2(*(uint32_t*)&m0h);
                    e1 = h2ex2(*(uint32_t*)&m1h);
                    float2 f0 = __half22float2(*(__half2*)&e0);
                    float2 f1 = __half22float2(*(__half2*)&e1);
                    rs[i][0] += f0.x + f0.y;
                    rs[i][1] += f1.x + f1.y;
                }
                *(uint32_t*)(C + (size_t)r0*ldc + cc)     = e0;
                *(uint32_t*)(C + (size_t)(r0+8)*ldc + cc) = e1;
            }
        }
        float* rz = rsum + (size_t)z * MPAD;
        #pragma unroll
        for (int i = 0; i < WM/16; i++){
            int r0 = m0 + wm*WM + i*16 + (lane >> 2);
            #pragma unroll
            for (int rr = 0; rr < 2; rr++){
                float s = rs[i][rr];
                s += __shfl_xor_sync(0xffffffffu, s, 1);
                s += __shfl_xor_sync(0xffffffffu, s, 2);
                if ((lane & 3) == 0 && s != 0.f) atomicAdd(&rz[r0 + rr*8], s);
            }
        }
    } else {
        const int w = z >> 1, h = z & 1;
        const int q0 = m0 / NTUP;
        const int qb = (q0 + 1) * NTUP;
        const float* rz = rsum + (size_t)z * MPAD;
        float s0 = 0.f, s1 = 0.f;
        #pragma unroll
        for (int i = 0; i < WM/16; i++){
            int rb = m0 + wm*WM + i*16 + (lane >> 2);
            #pragma unroll
            for (int rr = 0; rr < 2; rr++){
                int row = rb + rr*8;
                if (row < KROWS) {
                    const float inv = 1.f / rz[row];
                    const __half* qrow = qv + (size_t)row*DIM + h*DH;
                    float part = 0.f;
                    #pragma unroll
                    for (int jj = 0; jj < WN/8; jj++){
                        int cc = n0 + wn*WN + jj*8 + (lane & 3)*2;
                        float2 v = __half22float2(*(__half2*)&acc[i][jj][rr]);
                        float2 q2 = __half22float2(*(const __half2*)(qrow + cc));
                        float d0 = q2.x - v.x*inv;
                        float d1 = q2.y - v.y*inv;
                        part += d0*d0 + d1*d1;
                    }
                    if (row >= qb) s1 += part; else s0 += part;
                }
            }
        }
        float* red = (float*)smem;
        red[tid] = s0; red[256 + tid] = s1;
        __syncthreads();
        #pragma unroll
        for (int st = 128; st > 0; st >>= 1){
            if (tid < st) { red[tid] += red[tid+st]; red[256+tid] += red[256+tid+st]; }
            __syncthreads();
        }
        if (tid == 0 && red[0]   != 0.f) atomicAdd(&out[q0*WAY + w], -red[0]   * (1.f/NTUP));
        if (tid == 1 && q0 + 1 < NQ && red[256] != 0.f)
            atomicAdd(&out[(q0+1)*WAY + w], -red[256] * (1.f/NTUP));
    }
}

// ---------------- tuple combine + bias + LayerNorm (half2 I/O, shuffle reductions) ----------------
__global__ __launch_bounds__(192) void k_combine(
    const float* __restrict__ kb, const float* __restrict__ vb,
    const float* __restrict__ lg, const float* __restrict__ lb)
{
    const int bid = blockIdx.x;
    const int v = bid / NTUP, t = bid % NTUP;
    const int tid = threadIdx.x, lane = tid & 31, wrp = tid >> 5;
    __shared__ float redS[6], redQ[6];
    __shared__ int fr[3];
    if (tid < 3) fr[tid] = g_tuples[t*3 + tid];
    __syncthreads();

    const __half2* Pb[3];
    #pragma unroll
    for (int j = 0; j < 3; j++)
        Pb[j] = (const __half2*)(g_P + (size_t)(v*SEQ + fr[j])*6912) + j*1152;

    float2 kv[3], vv[3];
    float lsum = 0.f, lsq = 0.f;
    #pragma unroll
    for (int ii = 0; ii < 3; ii++) {
        int i = tid + ii*192;            // half2 index in [0,576)
        int d0 = 2*i;
        float2 ka = *(const float2*)(kb + d0);
        float2 va = *(const float2*)(vb + d0);
        #pragma unroll
        for (int j = 0; j < 3; j++) {
            float2 pk = __half22float2(Pb[j][i]);
            float2 pv = __half22float2(Pb[j][576 + i]);
            ka.x += pk.x; ka.y += pk.y;
            va.x += pv.x; va.y += pv.y;
        }
        kv[ii] = ka; vv[ii] = va;
        lsum += ka.x + ka.y;
        lsq  += ka.x*ka.x + ka.y*ka.y;
    }
    #pragma unroll
    for (int o = 16; o; o >>= 1) {
        lsum += __shfl_xor_sync(0xffffffffu, lsum, o);
        lsq  += __shfl_xor_sync(0xffffffffu, lsq,  o);
    }
    if (lane == 0) { redS[wrp] = lsum; redQ[wrp] = lsq; }
    __syncthreads();
    if (tid == 0) {
        float s = 0.f, q = 0.f;
        #pragma unroll
        for (int wv = 0; wv < 6; wv++) { s += redS[wv]; q += redQ[wv]; }
        redS[0] = s; redQ[0] = q;
    }
    __syncthreads();
    float mu = redS[0] * (1.f/1152.f);
    float var = redQ[0] * (1.f/1152.f) - mu*mu;
    float rstd = rsqrtf(var + 1e-5f);

    int w = 0, s = 0;
    if (v < NS) { w = v / SHOT; s = v % SHOT; }
    #pragma unroll
    for (int ii = 0; ii < 3; ii++) {
        int i = tid + ii*192;
        int d0 = 2*i;
        int h = (d0 >= DH) ? 1 : 0;
        int dd = d0 - h*DH;
        float2 g = *(const float2*)(lg + d0);
        float2 b = *(const float2*)(lb + d0);
        float ox = ((kv[ii].x - mu)*rstd*g.x + b.x) * RS24;
        float oy = ((kv[ii].y - mu)*rstd*g.y + b.y) * RS24;
        __half2 oh = __floats2half2_rn(ox, oy);
        __half2 vh = __floats2half2_rn(vv[ii].x, vv[ii].y);
        if (v < NS) {
            int zz = w*2 + h;
            *(__half2*)&g_skz[zz][(size_t)(s*NTUP + t)*DH + dd] = oh;
            int col = s*NTUP + t;
            g_svT[zz][(size_t)dd*KPAD + col]     = __low2half(vh);
            g_svT[zz][(size_t)(dd+1)*KPAD + col] = __high2half(vh);
        } else {
            *(__half2*)&g_qk[h][(size_t)((v-NS)*NTUP + t)*DH + dd] = oh;
            *(__half2*)&g_qv[(size_t)((v-NS)*NTUP + t)*DIM + d0] = vh;
        }
    }
}

// ---------------- launch ----------------
extern "C" void kernel_launch(void* const* d_in, const int* in_sizes, int n_in,
                              void* d_out, int out_size)
{
    const float* support = (const float*)d_in[0];
    const float* queries = (const float*)d_in[1];
    const float* k_w  = (const float*)d_in[3];
    const float* k_b  = (const float*)d_in[4];
    const float* v_w  = (const float*)d_in[5];
    const float* v_b  = (const float*)d_in[6];
    const float* ln_g = (const float*)d_in[7];
    const float* ln_b = (const float*)d_in[8];
    float* out = (float*)d_out;

    void *pAp, *pWT, *pP, *pQK, *pSKZ, *pSVT, *pATT, *pQV, *pRS;
    cudaGetSymbolAddress(&pAp,  g_Ap);
    cudaGetSymbolAddress(&pWT,  g_wT);
    cudaGetSymbolAddress(&pP,   g_P);
    cudaGetSymbolAddress(&pQK,  g_qk);
    cudaGetSymbolAddress(&pSKZ, g_skz);
    cudaGetSymbolAddress(&pSVT, g_svT);
    cudaGetSymbolAddress(&pATT, g_attn);
    cudaGetSymbolAddress(&pQV,  g_qv);
    cudaGetSymbolAddress(&pRS,  g_rowsum);

    auto gemm_pp = k_gemmh<0,32,32,4,2,3>;   // proj, 128x64 tiles
    auto gemm_sc = k_gemmh<1,32,64,4,2,3>;   // scores -> exp + rowsum
    auto gemm_pr = k_gemmh<2,64,48,2,4,2>;   // proto + normalize + logits
    cudaFuncSetAttribute(gemm_pp, cudaFuncAttributeMaxDynamicSharedMemorySize, 3*24576);
    cudaFuncSetAttribute(gemm_sc, cudaFuncAttributeMaxDynamicSharedMemorySize, 3*32768);
    cudaFuncSetAttribute(gemm_pr, cudaFuncAttributeMaxDynamicSharedMemorySize, 2*40960);

    // fork/join side stream (R8-proven capture pattern)
    cudaStream_t s1;
    cudaStreamCreateWithFlags(&s1, cudaStreamNonBlocking);
    cudaEvent_t e0, eA;
    cudaEventCreateWithFlags(&e0, cudaEventDisableTiming);
    cudaEventCreateWithFlags(&eA, cudaEventDisableTiming);

    k_init<<<1, 256>>>(out);
    cudaEventRecord(e0, 0);

    // side stream: rowsum zero + A-prep (overlaps transW on main)
    cudaStreamWaitEvent(s1, e0, 0);
    k_zrs<<<(WAY*HH*MPAD + 255)/256, 256, 0, s1>>>();
    k_prepA<<<NV*SEQ, 128, 0, s1>>>(support, queries);
    cudaEventRecord(eA, s1);

    k_transW<<<dim3(36, 36, 6), 256>>>(k_w, v_w);
    cudaStreamWaitEvent(0, eA, 0);

    // proj: P[1024(900), 6912] = Ap @ wT^T, K=1152, f16 out
    gemm_pp<<<dim3(108, 8, 1), 256, 3*24576>>>(
        (const __half*)pAp, DIM, 1, 0,
        (const __half*)pWT, DIM, 0,
        pP, 6912, 0, 18, nullptr, nullptr, nullptr);

    k_combine<<<NV*NTUP, 192>>>(k_b, v_b, ln_g, ln_b);

    // scores: per z: attn[11008,1152] = exp(qk[z%2] @ skz[z]^T), rowsum accumulated
    gemm_sc<<<dim3(9, 86, WAY*HH), 256, 3*32768>>>(
        (const __half*)pQK, DH, 2, (size_t)MPAD*DH,
        (const __half*)pSKZ, DH, (size_t)SKP*DH,
        pATT, SKP, (size_t)MPAD*SKP, 9, nullptr, nullptr, (float*)pRS);

    // proto + normalize + fused logits
    gemm_pr<<<dim3(3, 86, WAY*HH), 256, 2*40960>>>(
        (const __half*)pATT, KPAD, 0, (size_t)MPAD*KPAD,
        (const __half*)pSVT, KPAD, (size_t)DH*KPAD,
        nullptr, 0, 0, 18, (const __half*)pQV, out, (float*)pRS);
}